// round 12
// baseline (speedup 1.0000x reference)
#include <cuda_runtime.h>
#include <cuda_bf16.h>
#include <cstdint>

#define Bsz   8
#define Tlen  2048
#define Cdim  1024
#define Mrows (Bsz * Tlen)   // 16384
#define KPC   (Cdim / 2)     // 512 bf16-pairs per row

// Scratch (static device globals — no allocation in kernel_launch).
// g_xh/g_xm: time-mixed activations split into bf16 hi/mid, packed 2-per-u32.
// g_wh/g_wm: weights Wk/Wv/Wr split likewise. g_kvr: fp32 k/v/r outputs.
static __device__ __align__(256) unsigned g_xh[3ull * Mrows * KPC];
static __device__ __align__(256) unsigned g_xm[3ull * Mrows * KPC];
static __device__ __align__(256) unsigned g_wh[3ull * Cdim * KPC];
static __device__ __align__(256) unsigned g_wm[3ull * Cdim * KPC];
static __device__ __align__(256) float    g_kvr[3ull * Mrows * Cdim];
static __device__ __align__(256) float    g_z[Bsz * Cdim];

// ---------------------------------------------------------------------------
// bf16 split helpers: x = h + m, h = bf16(x), m = bf16(x - h).
// Packed word: low 16 bits = even-k element, high 16 = odd-k element.
// ---------------------------------------------------------------------------
__device__ __forceinline__ void split2(float x0, float x1,
                                       unsigned& ph, unsigned& pm) {
    __nv_bfloat16 h0 = __float2bfloat16_rn(x0);
    __nv_bfloat16 h1 = __float2bfloat16_rn(x1);
    __nv_bfloat16 m0 = __float2bfloat16_rn(x0 - __bfloat162float(h0));
    __nv_bfloat16 m1 = __float2bfloat16_rn(x1 - __bfloat162float(h1));
    __nv_bfloat162 vh = __halves2bfloat162(h0, h1);   // .x -> low 16 bits
    __nv_bfloat162 vm = __halves2bfloat162(m0, m1);
    ph = *(unsigned*)&vh;
    pm = *(unsigned*)&vm;
}

// ---------------------------------------------------------------------------
// 1) Fused embedding gather + time-mix + bf16 hi/mid split.
//    grid = B*T blocks, 256 threads; thread c4 owns channels 4c4..4c4+3
//    = packed kpairs {2c4, 2c4+1} (one uint2 per plane).
// ---------------------------------------------------------------------------
__global__ void mix_kernel(const int* __restrict__ toks,
                           const float* __restrict__ xx_init,
                           const float* __restrict__ emb,
                           const float* __restrict__ tmk,
                           const float* __restrict__ tmv,
                           const float* __restrict__ tmr) {
    const int bt = blockIdx.x;
    const int t  = bt & (Tlen - 1);
    const int b  = bt >> 11;
    const int c4 = threadIdx.x;            // 0..255

    const float4* emb4 = (const float4*)emb;
    const int tok = toks[bt];
    float4 xc = emb4[(size_t)tok * (Cdim / 4) + c4];

    float4 xp;
    if (t > 0) {
        const int tokp = toks[bt - 1];
        xp = emb4[(size_t)tokp * (Cdim / 4) + c4];
    } else {
        xp = ((const float4*)xx_init)[b * (Cdim / 4) + c4];
    }

    const float4 mk = ((const float4*)tmk)[c4];
    const float4 mv = ((const float4*)tmv)[c4];
    const float4 mr = ((const float4*)tmr)[c4];

    uint2* xh2 = (uint2*)g_xh;
    uint2* xm2 = (uint2*)g_xm;
    const size_t MQ2 = (size_t)Mrows * (KPC / 2);   // uint2 units per plane
    const size_t base = (size_t)bt * (KPC / 2) + c4;

    float4 o;
    uint2 ph, pm;
    // z = 0 : xk
    o.x = fmaf(mk.x, xc.x - xp.x, xp.x);
    o.y = fmaf(mk.y, xc.y - xp.y, xp.y);
    o.z = fmaf(mk.z, xc.z - xp.z, xp.z);
    o.w = fmaf(mk.w, xc.w - xp.w, xp.w);
    split2(o.x, o.y, ph.x, pm.x);
    split2(o.z, o.w, ph.y, pm.y);
    xh2[0 * MQ2 + base] = ph;
    xm2[0 * MQ2 + base] = pm;
    // z = 1 : xv
    o.x = fmaf(mv.x, xc.x - xp.x, xp.x);
    o.y = fmaf(mv.y, xc.y - xp.y, xp.y);
    o.z = fmaf(mv.z, xc.z - xp.z, xp.z);
    o.w = fmaf(mv.w, xc.w - xp.w, xp.w);
    split2(o.x, o.y, ph.x, pm.x);
    split2(o.z, o.w, ph.y, pm.y);
    xh2[1 * MQ2 + base] = ph;
    xm2[1 * MQ2 + base] = pm;
    // z = 2 : xr
    o.x = fmaf(mr.x, xc.x - xp.x, xp.x);
    o.y = fmaf(mr.y, xc.y - xp.y, xp.y);
    o.z = fmaf(mr.z, xc.z - xp.z, xp.z);
    o.w = fmaf(mr.w, xc.w - xp.w, xp.w);
    split2(o.x, o.y, ph.x, pm.x);
    split2(o.z, o.w, ph.y, pm.y);
    xh2[2 * MQ2 + base] = ph;
    xm2[2 * MQ2 + base] = pm;
}

// ---------------------------------------------------------------------------
// 1b) Weight prep: split Wk/Wv/Wr into packed bf16 hi/mid planes.
//     grid = (Cdim, 3), 256 threads; thread c4 owns one float4 of a row.
// ---------------------------------------------------------------------------
__global__ void wprep_kernel(const float* __restrict__ Wk,
                             const float* __restrict__ Wv,
                             const float* __restrict__ Wr) {
    const int row = blockIdx.x;
    const int z   = blockIdx.y;
    const int c4  = threadIdx.x;
    const float* W = (z == 0) ? Wk : ((z == 1) ? Wv : Wr);

    float4 v = ((const float4*)(W + (size_t)row * Cdim))[c4];
    uint2 ph, pm;
    split2(v.x, v.y, ph.x, pm.x);
    split2(v.z, v.w, ph.y, pm.y);
    const size_t idx = ((size_t)z * Cdim + row) * (KPC / 2) + c4;
    ((uint2*)g_wh)[idx] = ph;
    ((uint2*)g_wm)[idx] = pm;
}

// ---------------------------------------------------------------------------
// bf16 m16n8k16 mma
// ---------------------------------------------------------------------------
__device__ __forceinline__ void mma_bf16(float c[4],
                                         const unsigned a[4],
                                         const unsigned b[2]) {
    asm volatile(
        "mma.sync.aligned.m16n8k16.row.col.f32.bf16.bf16.f32 "
        "{%0,%1,%2,%3}, {%4,%5,%6,%7}, {%8,%9}, {%0,%1,%2,%3};"
        : "+f"(c[0]), "+f"(c[1]), "+f"(c[2]), "+f"(c[3])
        : "r"(a[0]), "r"(a[1]), "r"(a[2]), "r"(a[3]),
          "r"(b[0]), "r"(b[1]));
}

// ---------------------------------------------------------------------------
// 2) 3-pass bf16 tensor-core GEMM: C[m,n] = sum_k A[m,k] * W[n,k]  (K = 1024)
//    CTA tile 128(m) x 64(n), BK=16 (8 packed kpairs), 256 threads = 8 warps
//    in 4(m) x 2(n), each warp 32x32 = 2x4 m16n8k16 fragments.
//    Precision: acc += ah*bh + ah*bm + am*bh  (am*bm ~2^-18, dropped).
//    Smem [kp][m]/[kp][n], strides 136/72 words -> fragment-load addresses
//    mod 32 = 8*tig+g, a perfect bank permutation (conflict-free).
//    grid = (16, 128, 3); z==2 applies sigmoid (r).
// ---------------------------------------------------------------------------
#define ASTR 136
#define BSTR 72
#define KP   8    // kpairs per tile

__global__ void __launch_bounds__(256, 2)
gemm_kernel() {
    const int z = blockIdx.z;
    const unsigned* __restrict__ Axh = g_xh + (size_t)z * Mrows * KPC;
    const unsigned* __restrict__ Axm = g_xm + (size_t)z * Mrows * KPC;
    const unsigned* __restrict__ Bwh = g_wh + (size_t)z * Cdim * KPC;
    const unsigned* __restrict__ Bwm = g_wm + (size_t)z * Cdim * KPC;
    float* __restrict__ Co = g_kvr + (size_t)z * Mrows * Cdim;

    __shared__ unsigned Ah[KP][ASTR];
    __shared__ unsigned Am[KP][ASTR];
    __shared__ unsigned Bh[KP][BSTR];
    __shared__ unsigned Bm[KP][BSTR];

    const int tid  = threadIdx.x;
    const int warp = tid >> 5;
    const int lane = tid & 31;
    const int wm = warp & 3;     // 0..3 -> m offset wm*32
    const int wn = warp >> 2;    // 0..1 -> n offset wn*32
    const int g   = lane >> 2;   // group id 0..7
    const int tig = lane & 3;    // thread-in-group 0..3

    // tile loaders:
    // A: row = tid&127, half = tid>>7 -> kpairs [half*4, half*4+4)  (uint4)
    // B: row = tid&63,  part = tid>>6 -> kpairs [part*2, part*2+2)  (uint2)
    const int ar = tid & 127, ah4 = (tid >> 7) * 4;
    const int br = tid & 63,  bp2 = ((tid >> 6) & 3) * 2;
    const unsigned* aph = Axh + (size_t)(blockIdx.y * 128 + ar) * KPC + ah4;
    const unsigned* apm = Axm + (size_t)(blockIdx.y * 128 + ar) * KPC + ah4;
    const unsigned* bph = Bwh + (size_t)(blockIdx.x * 64  + br) * KPC + bp2;
    const unsigned* bpm = Bwm + (size_t)(blockIdx.x * 64  + br) * KPC + bp2;

    float acc[2][4][4];
    #pragma unroll
    for (int mi = 0; mi < 2; mi++)
        #pragma unroll
        for (int ni = 0; ni < 4; ni++)
            #pragma unroll
            for (int q = 0; q < 4; q++) acc[mi][ni][q] = 0.f;

    // prologue loads (first k-tile)
    uint4 avh = *(const uint4*)aph;
    uint4 avm = *(const uint4*)apm;
    uint2 bvh = *(const uint2*)bph;
    uint2 bvm = *(const uint2*)bpm;

    for (int k0 = 0; k0 < KPC; k0 += KP) {
        Ah[ah4 + 0][ar] = avh.x; Ah[ah4 + 1][ar] = avh.y;
        Ah[ah4 + 2][ar] = avh.z; Ah[ah4 + 3][ar] = avh.w;
        Am[ah4 + 0][ar] = avm.x; Am[ah4 + 1][ar] = avm.y;
        Am[ah4 + 2][ar] = avm.z; Am[ah4 + 3][ar] = avm.w;
        Bh[bp2 + 0][br] = bvh.x; Bh[bp2 + 1][br] = bvh.y;
        Bm[bp2 + 0][br] = bvm.x; Bm[bp2 + 1][br] = bvm.y;
        __syncthreads();

        // prefetch next k-tile (LDG latency overlaps the MMAs below)
        if (k0 + KP < KPC) {
            avh = *(const uint4*)(aph + k0 + KP);
            avm = *(const uint4*)(apm + k0 + KP);
            bvh = *(const uint2*)(bph + k0 + KP);
            bvm = *(const uint2*)(bpm + k0 + KP);
        }

        unsigned fah[2][4], fam[2][4];
        #pragma unroll
        for (int mi = 0; mi < 2; mi++) {
            const int mb = wm * 32 + mi * 16;
            fah[mi][0] = Ah[tig    ][mb + g    ];
            fah[mi][1] = Ah[tig    ][mb + g + 8];
            fah[mi][2] = Ah[tig + 4][mb + g    ];
            fah[mi][3] = Ah[tig + 4][mb + g + 8];
            fam[mi][0] = Am[tig    ][mb + g    ];
            fam[mi][1] = Am[tig    ][mb + g + 8];
            fam[mi][2] = Am[tig + 4][mb + g    ];
            fam[mi][3] = Am[tig + 4][mb + g + 8];
        }
        unsigned fbh[4][2], fbm[4][2];
        #pragma unroll
        for (int ni = 0; ni < 4; ni++) {
            const int nb = wn * 32 + ni * 8;
            fbh[ni][0] = Bh[tig    ][nb + g];
            fbh[ni][1] = Bh[tig + 4][nb + g];
            fbm[ni][0] = Bm[tig    ][nb + g];
            fbm[ni][1] = Bm[tig + 4][nb + g];
        }
        #pragma unroll
        for (int mi = 0; mi < 2; mi++)
            #pragma unroll
            for (int ni = 0; ni < 4; ni++) {
                mma_bf16(acc[mi][ni], fah[mi], fbh[ni]);
                mma_bf16(acc[mi][ni], fah[mi], fbm[ni]);
                mma_bf16(acc[mi][ni], fam[mi], fbh[ni]);
            }
        __syncthreads();
    }

    // epilogue: c0 @ (row, col), c1 @ (row, col+1), c2/c3 @ row+8
    const bool sig = (z == 2);
    #pragma unroll
    for (int mi = 0; mi < 2; mi++) {
        #pragma unroll
        for (int ni = 0; ni < 4; ni++) {
            const int row = blockIdx.y * 128 + wm * 32 + mi * 16 + g;
            const int col = blockIdx.x * 64  + wn * 32 + ni * 8 + tig * 2;
            float c0 = acc[mi][ni][0], c1 = acc[mi][ni][1];
            float c2 = acc[mi][ni][2], c3 = acc[mi][ni][3];
            if (sig) {
                c0 = 1.f / (1.f + __expf(-c0));
                c1 = 1.f / (1.f + __expf(-c1));
                c2 = 1.f / (1.f + __expf(-c2));
                c3 = 1.f / (1.f + __expf(-c3));
            }
            *(float2*)&Co[(size_t)row * Cdim + col]       = make_float2(c0, c1);
            *(float2*)&Co[(size_t)(row + 8) * Cdim + col] = make_float2(c2, c3);
        }
    }
}

// ---------------------------------------------------------------------------
// 3) WKV scan + fold of r*wkv into (ylast, ysum) -> g_z.
//    One thread per (b,c) channel: 8192 threads, 8-deep register prefetch
//    ring to hide DRAM latency behind the ~30-cycle carry chain.
// ---------------------------------------------------------------------------
__global__ void wkv_kernel(const float* __restrict__ aa_init,
                           const float* __restrict__ bb_init,
                           const float* __restrict__ pp_init,
                           const float* __restrict__ time_decay,
                           const float* __restrict__ time_first) {
    const int tid = blockIdx.x * blockDim.x + threadIdx.x;  // 0..8191
    const int b = tid >> 10;
    const int c = tid & (Cdim - 1);

    const size_t MC = (size_t)Mrows * Cdim;
    const float* kp = g_kvr + (size_t)(b * Tlen) * Cdim + c;
    const float* vp = kp + MC;
    const float* rp = kp + 2 * MC;

    const float w = -__expf(time_decay[c]);
    const float u = time_first[c];
    float aa = aa_init[tid], bb = bb_init[tid], pp = pp_init[tid];

    const int PF = 8;
    float kb[PF], vb[PF], rb[PF];
    #pragma unroll
    for (int j = 0; j < PF; j++) {
        const size_t o = (size_t)j * Cdim;
        kb[j] = kp[o]; vb[j] = vp[o]; rb[j] = rp[o];
    }

    float ysum = 0.f, ylast = 0.f;
    for (int t0 = 0; t0 < Tlen; t0 += PF) {
        #pragma unroll
        for (int j = 0; j < PF; j++) {
            const float kt = kb[j], vt = vb[j], rt = rb[j];
            const int tn = t0 + PF + j;
            if (tn < Tlen) {
                const size_t o = (size_t)tn * Cdim;
                kb[j] = kp[o]; vb[j] = vp[o]; rb[j] = rp[o];
            }
            // output
            const float ww = u + kt;
            const float p  = fmaxf(pp, ww);
            const float e1 = __expf(pp - p);
            const float e2 = __expf(ww - p);
            const float wkv = (e1 * aa + e2 * vt) / (e1 * bb + e2);
            const float y = rt * wkv;
            ysum += y;
            ylast = y;
            // state update
            const float ww2 = pp + w;
            const float p2  = fmaxf(ww2, kt);
            const float e1b = __expf(ww2 - p2);
            const float e2b = __expf(kt - p2);
            aa = e1b * aa + e2b * vt;
            bb = e1b * bb + e2b;
            pp = p2;
        }
    }
    g_z[tid] = 0.5f * (ylast + ysum * (1.0f / Tlen));
}

// ---------------------------------------------------------------------------
// 4) Final tiny GEMM: hx[b,d] = sum_c g_z[b,c] * Wo[d,c]; out = stack([hx,hx]).
//    One warp per (b,d) output.  8192 warps.
// ---------------------------------------------------------------------------
__global__ void out_kernel(const float* __restrict__ Wo,
                           float* __restrict__ out) {
    const int gw   = (blockIdx.x * blockDim.x + threadIdx.x) >> 5;  // 0..8191
    const int lane = threadIdx.x & 31;
    const int b = gw >> 10;
    const int d = gw & (Cdim - 1);

    const float4* wr = (const float4*)(Wo + (size_t)d * Cdim);
    const float4* zr = (const float4*)(g_z + b * Cdim);

    float s = 0.f;
    #pragma unroll
    for (int i = lane; i < Cdim / 4; i += 32) {
        const float4 wv = wr[i];
        const float4 zv = zr[i];
        s += wv.x * zv.x + wv.y * zv.y + wv.z * zv.z + wv.w * zv.w;
    }
    #pragma unroll
    for (int off = 16; off; off >>= 1) s += __shfl_down_sync(0xffffffffu, s, off);
    if (lane == 0) {
        out[gw] = s;
        out[Bsz * Cdim + gw] = s;   // stack([hx, hx])
    }
}

// ---------------------------------------------------------------------------
extern "C" void kernel_launch(void* const* d_in, const int* in_sizes, int n_in,
                              void* d_out, int out_size) {
    const int*   toks = (const int*)  d_in[0];
    const float* xx   = (const float*)d_in[1];
    const float* aai  = (const float*)d_in[2];
    const float* bbi  = (const float*)d_in[3];
    const float* ppi  = (const float*)d_in[4];
    const float* emb  = (const float*)d_in[5];
    const float* tmk  = (const float*)d_in[6];
    const float* tmv  = (const float*)d_in[7];
    const float* tmr  = (const float*)d_in[8];
    const float* tdec = (const float*)d_in[9];
    const float* tfir = (const float*)d_in[10];
    const float* Wk   = (const float*)d_in[11];
    const float* Wv   = (const float*)d_in[12];
    const float* Wr   = (const float*)d_in[13];
    const float* Wo   = (const float*)d_in[14];
    float* out = (float*)d_out;

    mix_kernel<<<Mrows, 256>>>(toks, xx, emb, tmk, tmv, tmr);
    wprep_kernel<<<dim3(Cdim, 3), 256>>>(Wk, Wv, Wr);
    gemm_kernel<<<dim3(Cdim / 64, Mrows / 128, 3), 256>>>();
    wkv_kernel<<<(Bsz * Cdim) / 64, 64>>>(aai, bbi, ppi, tdec, tfir);
    out_kernel<<<(Bsz * Cdim * 32) / 256, 256>>>(Wo, out);
}